// round 3
// baseline (speedup 1.0000x reference)
#include <cuda_runtime.h>
#include <cstdint>

#define N_NODES 500000
#define N_EDGES 1250000
#define IN_DIM  128
#define HID     64
#define N_GRAPHS 16384

// ---- scratch (static device globals: allocation-free rule) ----
__device__ float g_y  [(size_t)N_NODES * HID];
__device__ float g_agg[(size_t)N_NODES * HID];
__device__ float g_h  [(size_t)N_NODES * HID];
__device__ int   g_src[N_EDGES];
__device__ int   g_dst[N_EDGES];
__device__ int   g_batch[N_NODES];

// ---------------------------------------------------------------------------
// prep: detect int32 vs int64 indices (JAX may silently downcast int64->int32)
// and convert edge_index / batch into int32 scratch.
// Detection: word (N_NODES-1) is ODD; under int64 layout it is the high half
// of element (N-1)/2 => 0. Under int32 it is batch[N-1] = max graph id != 0.
// ---------------------------------------------------------------------------
__global__ void prep_kernel(const void* __restrict__ edge,
                            const void* __restrict__ batch) {
    const bool mode64 = (((const int*)batch)[N_NODES - 1] == 0);
    int t = blockIdx.x * blockDim.x + threadIdx.x;
    if (t < N_EDGES) {
        if (mode64) {
            g_src[t] = (int)((const long long*)edge)[t];
            g_dst[t] = (int)((const long long*)edge)[N_EDGES + t];
        } else {
            g_src[t] = ((const int*)edge)[t];
            g_dst[t] = ((const int*)edge)[N_EDGES + t];
        }
    }
    if (t < N_NODES) {
        g_batch[t] = mode64 ? (int)((const long long*)batch)[t]
                            : ((const int*)batch)[t];
    }
}

// ---------------------------------------------------------------------------
// GEMM 1 (plain): C[N,64] = A[N,K] @ W[K,64]         (K = 128 or 64)
// Block tile 128x64, BK=32, 256 threads, per-thread 8x4 register tile.
// A chunk stored transposed in SMEM (stride 132 keeps 16B alignment,
// conflict-free vectorized reads).
// ---------------------------------------------------------------------------
template<int K>
__global__ __launch_bounds__(256) void mm_plain(const float* __restrict__ A,
                                                const float* __restrict__ W,
                                                float* __restrict__ C) {
    __shared__ float As[32][132];
    __shared__ float Ws[32][64];
    const int tid = threadIdx.x;
    const int tx = tid & 15;   // col group -> cols tx*4 .. tx*4+3
    const int ty = tid >> 4;   // row group -> rows ty*8 .. ty*8+7
    const int rowBase = blockIdx.x * 128;
    float acc[8][4] = {};

    for (int k0 = 0; k0 < K; k0 += 32) {
        // A tile (transposed store)
        #pragma unroll
        for (int s = 0; s < 4; ++s) {
            int idx = tid + s * 256;           // 0..1023
            int row = idx >> 3;                // 0..127
            int kg  = (idx & 7) * 4;           // 0,4,..,28
            float4 v = make_float4(0.f, 0.f, 0.f, 0.f);
            int gr = rowBase + row;
            if (gr < N_NODES)
                v = *(const float4*)&A[(size_t)gr * K + k0 + kg];
            As[kg + 0][row] = v.x; As[kg + 1][row] = v.y;
            As[kg + 2][row] = v.z; As[kg + 3][row] = v.w;
        }
        // W tile
        #pragma unroll
        for (int s = 0; s < 2; ++s) {
            int idx = tid + s * 256;           // 0..511
            int k  = idx >> 4;                 // 0..31
            int cg = (idx & 15) * 4;
            *(float4*)&Ws[k][cg] = *(const float4*)&W[(size_t)(k0 + k) * 64 + cg];
        }
        __syncthreads();
        #pragma unroll
        for (int kk = 0; kk < 32; ++kk) {
            float4 w4 = *(const float4*)&Ws[kk][tx * 4];
            float4 a0 = *(const float4*)&As[kk][ty * 8];
            float4 a1 = *(const float4*)&As[kk][ty * 8 + 4];
            float a[8] = {a0.x, a0.y, a0.z, a0.w, a1.x, a1.y, a1.z, a1.w};
            float w[4] = {w4.x, w4.y, w4.z, w4.w};
            #pragma unroll
            for (int i = 0; i < 8; ++i)
                #pragma unroll
                for (int j = 0; j < 4; ++j)
                    acc[i][j] += a[i] * w[j];
        }
        __syncthreads();
    }
    #pragma unroll
    for (int i = 0; i < 8; ++i) {
        int gr = rowBase + ty * 8 + i;
        if (gr < N_NODES)
            *(float4*)&C[(size_t)gr * 64 + tx * 4] =
                make_float4(acc[i][0], acc[i][1], acc[i][2], acc[i][3]);
    }
}

// ---------------------------------------------------------------------------
// GEMM 2 (fused): U = relu(Y + AGG + ba);  C = relu(U @ W + bb)   (K = 64)
// ---------------------------------------------------------------------------
__global__ __launch_bounds__(256) void mm_fused(const float* __restrict__ Y,
                                                const float* __restrict__ AGG,
                                                const float* __restrict__ ba,
                                                const float* __restrict__ W,
                                                const float* __restrict__ bb,
                                                float* __restrict__ C) {
    __shared__ float As[32][132];
    __shared__ float Ws[32][64];
    const int tid = threadIdx.x;
    const int tx = tid & 15;
    const int ty = tid >> 4;
    const int rowBase = blockIdx.x * 128;
    float acc[8][4] = {};

    for (int k0 = 0; k0 < 64; k0 += 32) {
        #pragma unroll
        for (int s = 0; s < 4; ++s) {
            int idx = tid + s * 256;
            int row = idx >> 3;
            int kg  = (idx & 7) * 4;
            float4 v = make_float4(0.f, 0.f, 0.f, 0.f);
            int gr = rowBase + row;
            if (gr < N_NODES) {
                float4 y4 = *(const float4*)&Y  [(size_t)gr * 64 + k0 + kg];
                float4 a4 = *(const float4*)&AGG[(size_t)gr * 64 + k0 + kg];
                float4 b4 = *(const float4*)&ba[k0 + kg];
                v.x = fmaxf(y4.x + a4.x + b4.x, 0.f);
                v.y = fmaxf(y4.y + a4.y + b4.y, 0.f);
                v.z = fmaxf(y4.z + a4.z + b4.z, 0.f);
                v.w = fmaxf(y4.w + a4.w + b4.w, 0.f);
            }
            As[kg + 0][row] = v.x; As[kg + 1][row] = v.y;
            As[kg + 2][row] = v.z; As[kg + 3][row] = v.w;
        }
        #pragma unroll
        for (int s = 0; s < 2; ++s) {
            int idx = tid + s * 256;
            int k  = idx >> 4;
            int cg = (idx & 15) * 4;
            *(float4*)&Ws[k][cg] = *(const float4*)&W[(size_t)(k0 + k) * 64 + cg];
        }
        __syncthreads();
        #pragma unroll
        for (int kk = 0; kk < 32; ++kk) {
            float4 w4 = *(const float4*)&Ws[kk][tx * 4];
            float4 a0 = *(const float4*)&As[kk][ty * 8];
            float4 a1 = *(const float4*)&As[kk][ty * 8 + 4];
            float a[8] = {a0.x, a0.y, a0.z, a0.w, a1.x, a1.y, a1.z, a1.w};
            float w[4] = {w4.x, w4.y, w4.z, w4.w};
            #pragma unroll
            for (int i = 0; i < 8; ++i)
                #pragma unroll
                for (int j = 0; j < 4; ++j)
                    acc[i][j] += a[i] * w[j];
        }
        __syncthreads();
    }
    float4 bbv = *(const float4*)&bb[tx * 4];
    float bbs[4] = {bbv.x, bbv.y, bbv.z, bbv.w};
    #pragma unroll
    for (int i = 0; i < 8; ++i) {
        int gr = rowBase + ty * 8 + i;
        if (gr < N_NODES) {
            float4 o;
            o.x = fmaxf(acc[i][0] + bbs[0], 0.f);
            o.y = fmaxf(acc[i][1] + bbs[1], 0.f);
            o.z = fmaxf(acc[i][2] + bbs[2], 0.f);
            o.w = fmaxf(acc[i][3] + bbs[3], 0.f);
            *(float4*)&C[(size_t)gr * 64 + tx * 4] = o;
        }
    }
}

// ---------------------------------------------------------------------------
// Edge scatter: AGG[dst] += Y[src]  (16 threads per edge, float4 vector RED)
// ---------------------------------------------------------------------------
__global__ __launch_bounds__(256) void scatter_kernel(const float* __restrict__ Y,
                                                      float* __restrict__ AGG) {
    long long t = (long long)blockIdx.x * blockDim.x + threadIdx.x;
    if (t >= (long long)N_EDGES * 16) return;
    int e = (int)(t >> 4);
    int c = (int)(t & 15) * 4;
    int s = g_src[e];
    int d = g_dst[e];
    float4 v = *(const float4*)&Y[(size_t)s * 64 + c];
    atomicAdd((float4*)&AGG[(size_t)d * 64 + c], v);
}

// ---------------------------------------------------------------------------
// Head: per-graph pooled sum (batch is sorted -> binary search node range),
// then relu(pooled@wh1+bh1)@wh2+bh2.  One 64-thread block per graph.
// ---------------------------------------------------------------------------
__global__ __launch_bounds__(64) void head_kernel(const float* __restrict__ H,
                                                  const float* __restrict__ wh1,
                                                  const float* __restrict__ bh1,
                                                  const float* __restrict__ wh2,
                                                  const float* __restrict__ bh2,
                                                  float* __restrict__ out) {
    const int g = blockIdx.x;
    const int tid = threadIdx.x;
    __shared__ float pooled[64];
    __shared__ float red[64];
    __shared__ int range[2];
    if (tid < 2) {
        int target = g + tid;
        int lo = 0, hi = N_NODES;
        while (lo < hi) {
            int mid = (lo + hi) >> 1;
            if (g_batch[mid] < target) lo = mid + 1; else hi = mid;
        }
        range[tid] = lo;
    }
    __syncthreads();
    const int lo = range[0], hi = range[1];
    float p = 0.f;
    for (int i = lo; i < hi; ++i) p += H[(size_t)i * 64 + tid];
    pooled[tid] = p;
    __syncthreads();
    float u = bh1[tid];
    #pragma unroll
    for (int k = 0; k < 64; ++k) u += pooled[k] * wh1[k * 64 + tid];
    u = fmaxf(u, 0.f);
    red[tid] = u * wh2[tid];
    __syncthreads();
    if (tid < 32) red[tid] += red[tid + 32];
    __syncthreads();
    if (tid < 32) {
        float v = red[tid];
        #pragma unroll
        for (int off = 16; off; off >>= 1)
            v += __shfl_down_sync(0xffffffffu, v, off);
        if (tid == 0) out[g] = v + bh2[0];
    }
}

// ---------------------------------------------------------------------------
extern "C" void kernel_launch(void* const* d_in, const int* in_sizes, int n_in,
                              void* d_out, int out_size) {
    const float* x    = (const float*)d_in[0];
    const void*  edge = d_in[1];
    const void*  batc = d_in[2];
    const float* wh1  = (const float*)d_in[15];
    const float* bh1  = (const float*)d_in[16];
    const float* wh2  = (const float*)d_in[17];
    const float* bh2  = (const float*)d_in[18];

    float *yb, *aggb, *hb;
    cudaGetSymbolAddress((void**)&yb,   g_y);
    cudaGetSymbolAddress((void**)&aggb, g_agg);
    cudaGetSymbolAddress((void**)&hb,   g_h);

    const int mmGrid   = (N_NODES + 127) / 128;
    const int scatGrid = (int)(((long long)N_EDGES * 16 + 255) / 256);
    const size_t aggBytes = (size_t)N_NODES * HID * sizeof(float);

    prep_kernel<<<(N_EDGES + 255) / 256, 256>>>(edge, batc);

    for (int L = 0; L < 3; ++L) {
        const float* wa = (const float*)d_in[3 + 4 * L];
        const float* ba = (const float*)d_in[4 + 4 * L];
        const float* wb = (const float*)d_in[5 + 4 * L];
        const float* bb = (const float*)d_in[6 + 4 * L];
        if (L == 0) mm_plain<128><<<mmGrid, 256>>>(x,  wa, yb);
        else        mm_plain< 64><<<mmGrid, 256>>>(hb, wa, yb);
        cudaMemsetAsync(aggb, 0, aggBytes);
        scatter_kernel<<<scatGrid, 256>>>(yb, aggb);
        mm_fused<<<mmGrid, 256>>>(yb, aggb, ba, wb, bb, hb);
    }
    head_kernel<<<N_GRAPHS, 64>>>(hb, wh1, bh1, wh2, bh2, (float*)d_out);
}